// round 9
// baseline (speedup 1.0000x reference)
#include <cuda_runtime.h>
#include <cuda_bf16.h>

#define BATCH  64
#define NPTS   1024
#define CHUNKS 16
#define JCH    (NPTS / CHUNKS)      // 64 j per block
#define NJP    (JCH / 2)            // 32 j-pairs
#define TPB    256                  // thread t owns shifts 4t .. 4t+3

// Deterministic scratch (no device-side allocation; zero-initialized globals).
__device__ float g_partial[CHUNKS][BATCH][NPTS];  // 4 MB
__device__ float g_min[BATCH];
__device__ int   g_cnt_b[BATCH];
__device__ int   g_cnt_all;

typedef unsigned long long u64;

// ---- packed f32x2 helpers ---------------------------------------------------
__device__ __forceinline__ void upk2(u64 v, float& a, float& b) {
    asm("mov.b64 {%0, %1}, %2;" : "=f"(a), "=f"(b) : "l"(v));
}
__device__ __forceinline__ u64 pk2(float a, float b) {
    u64 r; asm("mov.b64 %0, {%1, %2};" : "=l"(r) : "f"(a), "f"(b)); return r;
}
__device__ __forceinline__ u64 addx2(u64 a, u64 b) {
    u64 r; asm("add.rn.f32x2 %0, %1, %2;" : "=l"(r) : "l"(a), "l"(b)); return r;
}
__device__ __forceinline__ u64 mulx2(u64 a, u64 b) {
    u64 r; asm("mul.rn.f32x2 %0, %1, %2;" : "=l"(r) : "l"(a), "l"(b)); return r;
}
__device__ __forceinline__ u64 fmx2(u64 a, u64 b, u64 c) {
    u64 r; asm("fma.rn.f32x2 %0, %1, %2, %3;" : "=l"(r) : "l"(a), "l"(b), "l"(c)); return r;
}
__device__ __forceinline__ float sqrtapx(float x) {
    float r; asm("sqrt.approx.f32 %0, %1;" : "=f"(r) : "f"(x)); return r;
}

// XOR swizzle on u64 pair index (range-preserving, no padding needed).
// Lane pattern p = C - 2t: within a group of 8 lanes the low 4 bits are the
// 8 distinct even (or odd) residues; across groups bits (p>>3)&6 separate.
__device__ __forceinline__ int swz(int p) { return p ^ ((p >> 3) & 6); }

// one packed distance-pair step: acc_lo/acc_hi += sqrt for both j's
#define DIST_ACC(AL, AH, TX, TY)                                \
    {                                                           \
        u64 dx = addx2(xpx, (TX)), dy = addx2(xpy, (TY));       \
        u64 d2 = fmx2(dy, dy, mulx2(dx, dx));                   \
        float lo, hi; upk2(d2, lo, hi);                         \
        AL += sqrtapx(lo); AH += sqrtapx(hi);                   \
    }

// ---------------------------------------------------------------------------
// Single fused kernel. Grid (CHUNKS, BATCH), TPB=256.
// Thread t owns shifts 4t..4t+3 and walks the chunk's j values in pairs.
// Negated target in one contiguous block of four u64-pair arrays:
//   SM[0]=even-x  SM[1]=odd-x  SM[2]=even-y  SM[3]=odd-y   (32 KB, swizzled)
// even pair v = (-T[2v],-T[2v+1]); odd pair v = (-T[2v+1],-T[2v+2]).
// Per q: 4 fresh LDS.64 (one base reg + imm offsets) + 2 broadcasts serve
// 8 distances; shifts m=2,3 reuse m=0,1's previous-iteration loads.
// ---------------------------------------------------------------------------
__global__ void __launch_bounds__(TPB, 6)
snake_kernel(const float2* __restrict__ x, const float2* __restrict__ tg,
             float* __restrict__ out)
{
    __shared__ __align__(16) u64 SM[4][NPTS];   // exactly 32 KB
    __shared__ u64 XPX[NJP], XPY[NJP];
    __shared__ float redmin[8];
    __shared__ int lastflag;

    const int b     = blockIdx.y;
    const int chunk = blockIdx.x;
    const int j0    = chunk * JCH;
    const int t     = threadIdx.x;

    const float2* __restrict__ tb = tg + b * NPTS;
    const float2* __restrict__ xb = x  + b * NPTS;

    float* EX = (float*)SM[0];   // even-x float view
    float* OX = (float*)SM[1];
    float* EY = (float*)SM[2];
    float* OY = (float*)SM[3];

    // Fill. Even element i in [0,2N): pair m=i>>1, slot i&1 holds -T[i mod N].
    // Odd  element i in [1,2N]: pair m=(i-1)>>1, slot (i-1)&1 holds -T[i mod N].
    #pragma unroll
    for (int i = t; i < 2 * NPTS + 1; i += TPB) {
        float2 tv = tb[i & (NPTS - 1)];
        float nx = -tv.x, ny = -tv.y;
        if (i < 2 * NPTS) {
            int pe = 2 * swz(i >> 1) + (i & 1);
            EX[pe] = nx;  EY[pe] = ny;
        }
        if (i >= 1) {
            int po = 2 * swz((i - 1) >> 1) + ((i - 1) & 1);
            OX[po] = nx;  OY[po] = ny;
        }
    }
    if (t < NJP) {
        float4 q = *(const float4*)(xb + j0 + 2 * t);   // (xj.x,xj.y,xj1.x,xj1.y)
        XPX[t] = pk2(q.x, q.z);
        XPY[t] = pk2(q.y, q.w);
    }
    __syncthreads();

    const int s0 = 4 * t;                       // first shift owned
    const int P  = ((j0 + NPTS) >> 1) - 2 * t;  // even pair index at q=0 (>= 2)

    float a0=0, a0h=0, a1=0, a1h=0, a2=0, a2h=0, a3=0, a3h=0;

    // Preload window: even pair P-1 (m=2), odd pair P-2 (m=3).
    int iw = swz(P - 1);
    int iz = swz(P - 2);
    u64 axe = SM[0][iw], aye = SM[2][iw];
    u64 axo = SM[1][iz], ayo = SM[3][iz];
    int fo = iw;                                // phi(P-1): odd index for q=0

    #pragma unroll 2
    for (int q = 0; q < NJP; ++q) {
        const int fe = swz(P + q);              // one swizzle + one base per q
        u64 bxe = SM[0][fe], bye = SM[2][fe];   // even pair v    (m=0)
        u64 bxo = SM[1][fo], byo = SM[3][fo];   // odd  pair v-1  (m=1)
        u64 xpx = XPX[q],    xpy = XPY[q];      // broadcast

        DIST_ACC(a0, a0h, bxe, bye)   // m=0
        DIST_ACC(a1, a1h, bxo, byo)   // m=1
        DIST_ACC(a2, a2h, axe, aye)   // m=2 (prev even)
        DIST_ACC(a3, a3h, axo, ayo)   // m=3 (prev odd)

        axe = bxe; aye = bye; axo = bxo; ayo = byo;
        fo = fe;
    }

    *(float4*)&g_partial[chunk][b][s0] =
        make_float4(a0 + a0h, a1 + a1h, a2 + a2h, a3 + a3h);

    // ---- last block of this batch reduces it --------------------------------
    __threadfence();
    if (t == 0) {
        int old = atomicAdd(&g_cnt_b[b], 1);
        lastflag = (old == CHUNKS - 1);
    }
    __syncthreads();
    if (!lastflag) return;
    __threadfence();
    if (t == 0) g_cnt_b[b] = 0;                        // reset for next replay

    float mn = 3.4e38f;
    #pragma unroll
    for (int k = 0; k < 4; ++k) {
        int s = t + k * TPB;
        float sum = 0.0f;
        #pragma unroll
        for (int c = 0; c < CHUNKS; ++c)
            sum += __ldcg(&g_partial[c][b][s]);
        mn = fminf(mn, sum);
    }
    #pragma unroll
    for (int o = 16; o > 0; o >>= 1)
        mn = fminf(mn, __shfl_xor_sync(0xFFFFFFFFu, mn, o));
    if ((t & 31) == 0) redmin[t >> 5] = mn;
    __syncthreads();

    if (t == 0) {
        float v = redmin[0];
        #pragma unroll
        for (int w = 1; w < 8; ++w) v = fminf(v, redmin[w]);
        g_min[b] = v;
        __threadfence();
        int old = atomicAdd(&g_cnt_all, 1);
        if (old == BATCH - 1) {                        // last batch-reducer
            g_cnt_all = 0;                             // reset for next replay
            float s = 0.0f;
            #pragma unroll
            for (int bb = 0; bb < BATCH; ++bb)
                s += __ldcg(&g_min[bb]);
            out[0] = s * (1.0f / (float)(BATCH * NPTS));
        }
    }
}

// ---------------------------------------------------------------------------
extern "C" void kernel_launch(void* const* d_in, const int* in_sizes, int n_in,
                              void* d_out, int out_size)
{
    const float2* x  = (const float2*)d_in[0];
    const float2* tg = (const float2*)d_in[1];
    float* out = (float*)d_out;

    dim3 grid(CHUNKS, BATCH);
    snake_kernel<<<grid, TPB>>>(x, tg, out);
}

// round 10
// speedup vs baseline: 1.2195x; 1.2195x over previous
#include <cuda_runtime.h>
#include <cuda_bf16.h>

#define BATCH  64
#define NPTS   1024
#define CHUNKS 32
#define JCH    (NPTS / CHUNKS)      // 32 j per block
#define NJP    (JCH / 2)            // 16 j-pairs
#define TPB    256                  // thread t owns shifts 4t .. 4t+3

// Deterministic scratch (no device-side allocation; zero-initialized globals).
__device__ float g_partial[CHUNKS][BATCH][NPTS];  // 8 MB
__device__ float g_min[BATCH];
__device__ int   g_cnt_b[BATCH];
__device__ int   g_cnt_all;

typedef unsigned long long u64;

// ---- packed f32x2 helpers ---------------------------------------------------
__device__ __forceinline__ void upk2(u64 v, float& a, float& b) {
    asm("mov.b64 {%0, %1}, %2;" : "=f"(a), "=f"(b) : "l"(v));   // reg-pair alias
}
__device__ __forceinline__ u64 pk2(float a, float b) {
    u64 r; asm("mov.b64 %0, {%1, %2};" : "=l"(r) : "f"(a), "f"(b)); return r;
}
__device__ __forceinline__ u64 addx2(u64 a, u64 b) {
    u64 r; asm("add.rn.f32x2 %0, %1, %2;" : "=l"(r) : "l"(a), "l"(b)); return r;
}
__device__ __forceinline__ u64 mulx2(u64 a, u64 b) {
    u64 r; asm("mul.rn.f32x2 %0, %1, %2;" : "=l"(r) : "l"(a), "l"(b)); return r;
}
__device__ __forceinline__ u64 fmx2(u64 a, u64 b, u64 c) {
    u64 r; asm("fma.rn.f32x2 %0, %1, %2, %3;" : "=l"(r) : "l"(a), "l"(b), "l"(c)); return r;
}
__device__ __forceinline__ float sqrtapx(float x) {
    float r; asm("sqrt.approx.f32 %0, %1;" : "=f"(r) : "f"(x)); return r;
}

#define DIST_ACC(AL, AH, TX, TY)                                \
    {                                                           \
        u64 dx = addx2(xpx, (TX)), dy = addx2(xpy, (TY));       \
        u64 d2 = fmx2(dy, dy, mulx2(dx, dx));                   \
        float lo, hi; upk2(d2, lo, hi);                         \
        AL += sqrtapx(lo); AH += sqrtapx(hi);                   \
    }

// ---------------------------------------------------------------------------
// Single fused kernel. Grid (CHUNKS, BATCH), TPB=256.
// R4's proven layout: negated target duplicated (2N) in plain SoA-free float2
// order (u64 pairs, NO swizzle — contiguity lets ptxas merge window loads
// into wide LDS across the unrolled loop, which measured faster than every
// swizzled variant). Thread t owns shifts 4t..4t+3:
//   m=0: pair (e,e+1)   = bxu (fresh u64 load)
//   m=1: (e-1,e)        = pk2(prev.hi, cur.lo)
//   m=2: (e-2,e-1)      = previous bxu (register)
//   m=3: (e-3,e-2)      = pk2(prevprev.hi, prev.lo)
// Only 4 pack MOVs per 8 distances. Reduction fused via last-block pattern.
// ---------------------------------------------------------------------------
__global__ void __launch_bounds__(TPB, 5)
snake_kernel(const float2* __restrict__ x, const float2* __restrict__ tg,
             float* __restrict__ out)
{
    __shared__ __align__(16) u64 TX64[NPTS + JCH + 8];  // even pairs of -t.x over 2N window
    __shared__ __align__(16) u64 TY64[NPTS + JCH + 8];
    __shared__ u64 XPX[NJP], XPY[NJP];
    __shared__ float redmin[8];
    __shared__ int lastflag;

    const int b     = blockIdx.y;
    const int chunk = blockIdx.x;
    const int j0    = chunk * JCH;
    const int t     = threadIdx.x;

    const float2* __restrict__ tb = tg + b * NPTS;
    const float2* __restrict__ xb = x  + b * NPTS;

    // Pair p covers target indices (2p, 2p+1) of the duplicated domain.
    // Needed p range: [0, (j0+NPTS)/2 + NJP). Fill [0, NPTS/2 + NJP/... full 2N/2+pad].
    float* TXf = (float*)TX64;
    float* TYf = (float*)TY64;
    #pragma unroll
    for (int i = t; i < 2 * (NPTS + JCH / 2 + 8); i += TPB) {
        float2 tv = tb[i & (NPTS - 1)];
        TXf[i] = -tv.x;
        TYf[i] = -tv.y;
    }
    if (t < NJP) {
        float4 q = *(const float4*)(xb + j0 + 2 * t);   // (xj.x,xj.y,xj1.x,xj1.y)
        XPX[t] = pk2(q.x, q.z);
        XPY[t] = pk2(q.y, q.w);
    }
    __syncthreads();

    const int s0 = 4 * t;                        // first shift owned
    const int P  = ((j0 + NPTS) >> 1) - 2 * t;   // even pair index at jj=0 (>= 2)

    float a0=0, a0h=0, a1=0, a1h=0, a2=0, a2h=0, a3=0, a3h=0;

    // Preload window: pair P-1 (m=2 uses it; halves feed m=1), and hi of P-2 (m=3).
    u64 axu = TX64[P - 1], ayu = TY64[P - 1];
    float axl, axh, ayl, ayh;
    upk2(axu, axl, axh); upk2(ayu, ayl, ayh);
    u64 pxu = TX64[P - 2], pyu = TY64[P - 2];
    float dum, cxh, cyh;
    upk2(pxu, dum, cxh); upk2(pyu, dum, cyh);

    #pragma unroll
    for (int jj = 0; jj < NJP; ++jj) {
        u64 bxu = TX64[P + jj];                  // fresh even pair (contiguous
        u64 byu = TY64[P + jj];                  //  across iters -> merged LDS)
        float bxl, bxh, byl, byh;
        upk2(bxu, bxl, bxh); upk2(byu, byl, byh);
        u64 xpx = XPX[jj], xpy = XPY[jj];        // broadcast

        u64 tx1 = pk2(axh, bxl), ty1 = pk2(ayh, byl);   // (e-1, e)
        u64 tx3 = pk2(cxh, axl), ty3 = pk2(cyh, ayl);   // (e-3, e-2)

        DIST_ACC(a0, a0h, bxu, byu)   // m=0
        DIST_ACC(a1, a1h, tx1, ty1)   // m=1
        DIST_ACC(a2, a2h, axu, ayu)   // m=2 (prev pair)
        DIST_ACC(a3, a3h, tx3, ty3)   // m=3

        cxh = axh; cyh = ayh;
        axu = bxu; ayu = byu;
        axl = bxl; axh = bxh; ayl = byl; ayh = byh;
    }

    *(float4*)&g_partial[chunk][b][s0] =
        make_float4(a0 + a0h, a1 + a1h, a2 + a2h, a3 + a3h);

    // ---- last block of this batch reduces it --------------------------------
    __threadfence();
    if (t == 0) {
        int old = atomicAdd(&g_cnt_b[b], 1);
        lastflag = (old == CHUNKS - 1);
    }
    __syncthreads();
    if (!lastflag) return;
    __threadfence();
    if (t == 0) g_cnt_b[b] = 0;                         // reset for next replay

    float mn = 3.4e38f;
    #pragma unroll
    for (int k = 0; k < 4; ++k) {
        int s = t + k * TPB;
        float sum = 0.0f;
        #pragma unroll
        for (int c = 0; c < CHUNKS; ++c)
            sum += __ldcg(&g_partial[c][b][s]);
        mn = fminf(mn, sum);
    }
    #pragma unroll
    for (int o = 16; o > 0; o >>= 1)
        mn = fminf(mn, __shfl_xor_sync(0xFFFFFFFFu, mn, o));
    if ((t & 31) == 0) redmin[t >> 5] = mn;
    __syncthreads();

    if (t == 0) {
        float v = redmin[0];
        #pragma unroll
        for (int w = 1; w < 8; ++w) v = fminf(v, redmin[w]);
        g_min[b] = v;
        __threadfence();
        int old = atomicAdd(&g_cnt_all, 1);
        if (old == BATCH - 1) {                         // last batch-reducer
            g_cnt_all = 0;                              // reset for next replay
            float s = 0.0f;
            #pragma unroll
            for (int bb = 0; bb < BATCH; ++bb)
                s += __ldcg(&g_min[bb]);
            out[0] = s * (1.0f / (float)(BATCH * NPTS));
        }
    }
}

// ---------------------------------------------------------------------------
extern "C" void kernel_launch(void* const* d_in, const int* in_sizes, int n_in,
                              void* d_out, int out_size)
{
    const float2* x  = (const float2*)d_in[0];
    const float2* tg = (const float2*)d_in[1];
    float* out = (float*)d_out;

    dim3 grid(CHUNKS, BATCH);
    snake_kernel<<<grid, TPB>>>(x, tg, out);
}